// round 6
// baseline (speedup 1.0000x reference)
#include <cuda_runtime.h>
#include <cstdint>

// ---------------------------------------------------------------------------
// out = concat( relu(A@relu(A@F)), A@(A@G) ), A:[8192,8192] f32, F,G:[8192,64]
// Per layer: fused GEMM C[8192,128] = A @ Bt^T, relu on cols [0,64).
// 4 MMA warps (32x64 reg tiles) + 4 producer warps; half-stage (K16)
// register double-buffered pipeline hides mbarrier+LDS under MMA bursts.
// ---------------------------------------------------------------------------

#define NN      8192
#define NB      128
#define MT      64            // M-tile per CTA -> 128 CTAs
#define KT      32            // K per stage
#define STAGES  4
#define KIT     (NN / KT)     // 256
#define AROW    36            // A smem row pitch (floats)
#define BROW    48            // B smem row pitch (floats)
#define A_STG_F (MT * AROW)   // 2304
#define B_STG_F (NB * BROW)   // 6144
#define STG_F   (A_STG_F + B_STG_F)       // 8448 floats
#define SMEM_BYTES (STAGES * STG_F * 4)   // 135168 B

__device__ float g_bt1[NB * NN];   // layer-1 B (K-permuted, tf32-rounded)
__device__ float g_bt2[NB * NN];   // layer-1 out transposed = layer-2 B

__device__ __forceinline__ int kperm(int k) {
    return (k & ~15) | ((k & 3) << 2) | ((k >> 2) & 3);
}

__device__ __forceinline__ uint32_t smem_u32(const void* p) {
    uint32_t a;
    asm("{ .reg .u64 t; cvta.to.shared.u64 t, %1; cvt.u32.u64 %0, t; }"
        : "=r"(a) : "l"(p));
    return a;
}

__device__ __forceinline__ float rna_tf32_f(float f) {
    uint32_t u;
    asm("cvt.rna.tf32.f32 %0, %1;" : "=r"(u) : "f"(f));
    return __uint_as_float(u);
}

#define CP_ASYNC16(dst, src) \
    asm volatile("cp.async.cg.shared.global [%0], [%1], 16;" \
                 :: "r"(dst), "l"(src) : "memory")

#define MBAR_INIT(addr, cnt) \
    asm volatile("mbarrier.init.shared.b64 [%0], %1;" :: "r"(addr), "r"(cnt) : "memory")
#define MBAR_ARRIVE(addr) \
    asm volatile("mbarrier.arrive.shared.b64 _, [%0];" :: "r"(addr) : "memory")
#define CP_ASYNC_MBAR_ARRIVE(addr) \
    asm volatile("cp.async.mbarrier.arrive.noinc.shared::cta.b64 [%0];" \
                 :: "r"(addr) : "memory")

#define MBAR_WAIT(addr, parity) do {                                          \
    uint32_t _mb = (addr); uint32_t _ph = (parity); uint32_t _done;           \
    asm volatile("{\n\t.reg .pred p;\n\t"                                     \
        "mbarrier.try_wait.parity.acquire.cta.shared::cta.b64 p, [%1], %2;\n\t"\
        "selp.b32 %0, 1, 0, p;\n\t}"                                          \
        : "=r"(_done) : "r"(_mb), "r"(_ph) : "memory");                       \
    if (!_done) {                                                             \
        asm volatile("{\n\t.reg .pred P1;\n\t"                                \
            "WL_%=:\n\t"                                                      \
            "mbarrier.try_wait.parity.acquire.cta.shared::cta.b64 P1, [%0], %1, 0x989680;\n\t" \
            "@P1 bra.uni WD_%=;\n\t"                                          \
            "bra.uni WL_%=;\n\t"                                              \
            "WD_%=:\n\t}"                                                     \
            :: "r"(_mb), "r"(_ph) : "memory");                                \
    }                                                                         \
} while (0)

__device__ __forceinline__ void mma_tf32(float* c, const uint32_t* a,
                                         const uint32_t* b) {
    asm volatile(
        "mma.sync.aligned.m16n8k8.row.col.f32.tf32.tf32.f32 "
        "{%0,%1,%2,%3}, {%4,%5,%6,%7}, {%8,%9}, {%0,%1,%2,%3};"
        : "+f"(c[0]), "+f"(c[1]), "+f"(c[2]), "+f"(c[3])
        : "r"(a[0]), "r"(a[1]), "r"(a[2]), "r"(a[3]), "r"(b[0]), "r"(b[1]));
}

// ---------------------------------------------------------------------------
__global__ void pack_bt_kernel(const float* __restrict__ F,
                               const float* __restrict__ G,
                               float* __restrict__ Bt) {
    __shared__ float tile[32][33];
    int kb = blockIdx.x * 32;
    int nb = blockIdx.y * 32;
    int tx = threadIdx.x, ty = threadIdx.y;   // block (32, 8)
    #pragma unroll
    for (int r = ty; r < 32; r += 8) {
        int k = kb + r, n = nb + tx;
        float v = (n < 64) ? F[(size_t)k * 64 + n] : G[(size_t)k * 64 + (n - 64)];
        tile[r][tx] = rna_tf32_f(v);
    }
    __syncthreads();
    #pragma unroll
    for (int r = ty; r < 32; r += 8) {
        int n = nb + r, k = kb + tx;
        Bt[(size_t)n * NN + kperm(k)] = tile[tx][r];
    }
}

// ---------------------------------------------------------------------------
__global__ void __launch_bounds__(256, 1)
gemm_layer(const float* __restrict__ A, const float* __restrict__ Bt,
           float* __restrict__ outT, float* __restrict__ outR) {
    extern __shared__ float smem[];
    __shared__ __align__(8) uint64_t mbar[2 * STAGES];   // [full x4][empty x4]

    const int tid  = threadIdx.x;
    const int lane = tid & 31;
    const int w    = tid >> 5;
    const int m0   = blockIdx.x * MT;
    const uint32_t sbase = smem_u32(smem);
    const uint32_t mb    = smem_u32(mbar);
    const int r4 = lane >> 2;
    const int c4 = lane & 3;

    if (tid == 0) {
        #pragma unroll
        for (int s = 0; s < STAGES; s++) {
            MBAR_INIT(mb + 8 * s, 128);                 // full: cp.async x128
            MBAR_INIT(mb + 8 * (STAGES + s), 128);      // empty: 128 consumers
        }
    }
    __syncthreads();

    if (w >= 4) {
        // ================= producers (warps 4-7) =================
        const int t = tid - 128;
        for (int it = 0; it < KIT; it++) {
            const int s = it & (STAGES - 1);
            const int r = it >> 2;
            if (r > 0) MBAR_WAIT(mb + 8 * (STAGES + s), (r - 1) & 1);
            const int k0 = it * KT;
            const uint32_t abase = sbase + (uint32_t)(s * STG_F) * 4u;
            const uint32_t bbase = abase + A_STG_F * 4u;
            #pragma unroll
            for (int j = 0; j < 4; j++) {               // A: 512 chunks
                int ch = t + 128 * j;
                int row = ch >> 3, cc = ch & 7;
                const float* src = A + (size_t)(m0 + row) * NN + k0 + cc * 4;
                CP_ASYNC16(abase + (uint32_t)(row * AROW + cc * 4) * 4u, src);
            }
            #pragma unroll
            for (int j = 0; j < 8; j++) {               // B: 1024 chunks
                int ch = t + 128 * j;
                int row = ch >> 3, cc = ch & 7;
                const float* src = Bt + (size_t)row * NN + k0 + cc * 4;
                CP_ASYNC16(bbase + (uint32_t)(row * BROW + cc * 4) * 4u, src);
            }
            CP_ASYNC_MBAR_ARRIVE(mb + 8 * s);
        }
        return;
    }

    // ================= MMA warps (0-3): 32 rows x 64 cols =================
    const int wm = w >> 1;       // rows wm*32 .. +31
    const int wn = w & 1;        // cols wn*64 .. +63

    float acc[2][8][4];
    #pragma unroll
    for (int mi = 0; mi < 2; mi++)
        #pragma unroll
        for (int ni = 0; ni < 8; ni++)
            #pragma unroll
            for (int j = 0; j < 4; j++) acc[mi][ni][j] = 0.f;

    // load half h (K16) of stage s into a register buffer
    auto load_half = [&](int s, int h, uint32_t aH[4][4], float4 bH[8]) {
        const float* As = smem + s * STG_F;
        const float* Bs = As + A_STG_F;
        const float* aP = As + (wm * 32 + r4) * AROW + c4 + 16 * h;
        #pragma unroll
        for (int g = 0; g < 4; g++)
            #pragma unroll
            for (int j = 0; j < 4; j++)
                aH[g][j] = __float_as_uint(aP[g * 8 * AROW + 4 * j]) + 0x1000u;
        #pragma unroll
        for (int g = 0; g < 8; g++) {
            const float4* bRow =
                (const float4*)(Bs + (wn * 64 + g * 8 + r4) * BROW);
            bH[g] = bRow[c4 + 4 * h];
        }
    };

    // 32 MMAs on one half-stage buffer
    auto mma_half = [&](uint32_t aH[4][4], float4 bH[8]) {
        #pragma unroll
        for (int ks = 0; ks < 2; ks++) {
            uint32_t af0[4] = { aH[0][2 * ks], aH[1][2 * ks],
                                aH[0][2 * ks + 1], aH[1][2 * ks + 1] };
            uint32_t af1[4] = { aH[2][2 * ks], aH[3][2 * ks],
                                aH[2][2 * ks + 1], aH[3][2 * ks + 1] };
            #pragma unroll
            for (int ni = 0; ni < 8; ni++) {
                uint32_t bf[2];
                if (ks) { bf[0] = __float_as_uint(bH[ni].z);
                          bf[1] = __float_as_uint(bH[ni].w); }
                else    { bf[0] = __float_as_uint(bH[ni].x);
                          bf[1] = __float_as_uint(bH[ni].y); }
                mma_tf32(acc[0][ni], af0, bf);
                mma_tf32(acc[1][ni], af1, bf);
            }
        }
    };

    uint32_t aA[4][4], aB[4][4];
    float4   bA[8],    bB[8];

    // prologue: stage 0 half 0 resident in buffer A
    MBAR_WAIT(mb + 0, 0);
    load_half(0, 0, aA, bA);

    for (int it = 0; it < KIT; it++) {
        const int s = it & (STAGES - 1);

        load_half(s, 1, aB, bB);          // this stage, half 1 -> buf B
        mma_half(aA, bA);                 // burst: stage it, half 0

        if (it + 1 < KIT) {               // next stage half 0 -> buf A
            const int s1 = (it + 1) & (STAGES - 1);
            MBAR_WAIT(mb + 8 * s1, ((it + 1) >> 2) & 1);
            load_half(s1, 0, aA, bA);
        }
        mma_half(aB, bB);                 // burst: stage it, half 1

        MBAR_ARRIVE(mb + 8 * (STAGES + s));   // stage it fully consumed
    }

    // ---- epilogue ----
    const int rBase = m0 + wm * 32 + r4;
    const int cBase = wn * 64 + c4 * 2;
    #pragma unroll
    for (int mi = 0; mi < 2; mi++) {
        #pragma unroll
        for (int ni = 0; ni < 8; ni++) {
            #pragma unroll
            for (int j = 0; j < 4; j++) {
                int row = rBase + mi * 16 + (j >> 1) * 8;
                int col = cBase + ni * 8 + (j & 1);
                float v = acc[mi][ni][j];
                if (col < 64) v = fmaxf(v, 0.0f);
                if (outT) outT[(size_t)col * NN + kperm(row)] = rna_tf32_f(v);
                else      outR[(size_t)row * NB + col] = v;
            }
        }
    }
}

// ---------------------------------------------------------------------------
extern "C" void kernel_launch(void* const* d_in, const int* in_sizes, int n_in,
                              void* d_out, int out_size) {
    (void)in_sizes; (void)n_in; (void)out_size;
    const float* A = (const float*)d_in[0];
    const float* F = (const float*)d_in[1];
    const float* G = (const float*)d_in[2];
    float* out = (float*)d_out;

    float *bt1 = nullptr, *bt2 = nullptr;
    cudaGetSymbolAddress((void**)&bt1, g_bt1);
    cudaGetSymbolAddress((void**)&bt2, g_bt2);

    cudaFuncSetAttribute(gemm_layer,
                         cudaFuncAttributeMaxDynamicSharedMemorySize, SMEM_BYTES);

    dim3 pb(32, 8), pg(NN / 32, NB / 32);
    pack_bt_kernel<<<pg, pb>>>(F, G, bt1);

    gemm_layer<<<NN / MT, 256, SMEM_BYTES>>>(A, bt1, bt2, nullptr);
    gemm_layer<<<NN / MT, 256, SMEM_BYTES>>>(A, bt2, nullptr, out);
}

// round 7
// speedup vs baseline: 1.7035x; 1.7035x over previous
#include <cuda_runtime.h>
#include <cuda_fp16.h>
#include <cstdint>

// ---------------------------------------------------------------------------
// out = concat( relu(A@relu(A@F)), A@(A@G) ), A:[8192,8192] f32, F,G:[8192,64]
// Per layer: fused GEMM C[8192,128] = A @ Bt^T, relu on cols [0,64).
// fp16 mma.m16n8k16 (same 10-bit mantissa as tf32, 2x MACs/instr).
// A scaled x2^13 (exact) to avoid fp16 subnormals; intermediates stored x2^6;
// epilogues undo with exact powers of two.
// ---------------------------------------------------------------------------

#define NN      8192
#define NB      128
#define MT      64              // M rows per CTA -> 128 CTAs
#define KT      32              // K per stage
#define STAGES  8
#define KIT     (NN / KT)       // 256
#define A_PITCH 160             // bytes per A smem row (40 words, %32==8)
#define B_PITCH 64              // bytes per B smem row (fp16 k32)
#define A_STG_B (64 * A_PITCH)  // 10240
#define B_STG_B (128 * B_PITCH) // 8192
#define STG_B   (A_STG_B + B_STG_B)        // 18432
#define SMEM_BYTES (STAGES * STG_B)        // 147456

__device__ __half g_bth1[NB * NN];   // layer-1 B, fp16 chunk-permuted
__device__ __half g_bth2[NB * NN];   // layer-1 out (x2^6) = layer-2 B

// chunk permutation within each k32 block (2-element chunks):
// chunk j -> position (j%4)*4 + j/4
__device__ __forceinline__ int kperm2(int k) {
    int j = (k >> 1) & 15;
    int p = ((j & 3) << 2) | (j >> 2);
    return (k & ~31) | (p << 1) | (k & 1);
}

__device__ __forceinline__ uint32_t smem_u32(const void* p) {
    uint32_t a;
    asm("{ .reg .u64 t; cvta.to.shared.u64 t, %1; cvt.u32.u64 %0, t; }"
        : "=r"(a) : "l"(p));
    return a;
}

// pack two fp32 -> fp16x2 (lo = first arg)
__device__ __forceinline__ uint32_t pack_h2(float lo, float hi) {
    uint32_t d;
    asm("cvt.rn.f16x2.f32 %0, %1, %2;" : "=r"(d) : "f"(hi), "f"(lo));
    return d;
}

#define CP_ASYNC16(dst, src) \
    asm volatile("cp.async.cg.shared.global [%0], [%1], 16;" \
                 :: "r"(dst), "l"(src) : "memory")

#define MBAR_INIT(addr, cnt) \
    asm volatile("mbarrier.init.shared.b64 [%0], %1;" :: "r"(addr), "r"(cnt) : "memory")
#define MBAR_ARRIVE(addr) \
    asm volatile("mbarrier.arrive.shared.b64 _, [%0];" :: "r"(addr) : "memory")
#define CP_ASYNC_MBAR_ARRIVE(addr) \
    asm volatile("cp.async.mbarrier.arrive.noinc.shared::cta.b64 [%0];" \
                 :: "r"(addr) : "memory")

#define MBAR_WAIT(addr, parity) do {                                          \
    uint32_t _mb = (addr); uint32_t _ph = (parity); uint32_t _done;           \
    asm volatile("{\n\t.reg .pred p;\n\t"                                     \
        "mbarrier.try_wait.parity.acquire.cta.shared::cta.b64 p, [%1], %2;\n\t"\
        "selp.b32 %0, 1, 0, p;\n\t}"                                          \
        : "=r"(_done) : "r"(_mb), "r"(_ph) : "memory");                       \
    if (!_done) {                                                             \
        asm volatile("{\n\t.reg .pred P1;\n\t"                                \
            "WL_%=:\n\t"                                                      \
            "mbarrier.try_wait.parity.acquire.cta.shared::cta.b64 P1, [%0], %1, 0x989680;\n\t" \
            "@P1 bra.uni WD_%=;\n\t"                                          \
            "bra.uni WL_%=;\n\t"                                              \
            "WD_%=:\n\t}"                                                     \
            :: "r"(_mb), "r"(_ph) : "memory");                                \
    }                                                                         \
} while (0)

__device__ __forceinline__ void mma_f16(float* c, const uint32_t* a,
                                        uint32_t b0, uint32_t b1) {
    asm volatile(
        "mma.sync.aligned.m16n8k16.row.col.f32.f16.f16.f32 "
        "{%0,%1,%2,%3}, {%4,%5,%6,%7}, {%8,%9}, {%0,%1,%2,%3};"
        : "+f"(c[0]), "+f"(c[1]), "+f"(c[2]), "+f"(c[3])
        : "r"(a[0]), "r"(a[1]), "r"(a[2]), "r"(a[3]), "r"(b0), "r"(b1));
}

// ---------------------------------------------------------------------------
// Pack F||G -> Bt[128][8192] fp16, chunk-permuted.
// ---------------------------------------------------------------------------
__global__ void pack_bt_kernel(const float* __restrict__ F,
                               const float* __restrict__ G,
                               __half* __restrict__ Bt) {
    __shared__ float tile[32][33];
    int kb = blockIdx.x * 32;
    int nb = blockIdx.y * 32;
    int tx = threadIdx.x, ty = threadIdx.y;   // block (32, 8)
    #pragma unroll
    for (int r = ty; r < 32; r += 8) {
        int k = kb + r, n = nb + tx;
        float v = (n < 64) ? F[(size_t)k * 64 + n] : G[(size_t)k * 64 + (n - 64)];
        tile[r][tx] = v;
    }
    __syncthreads();
    #pragma unroll
    for (int r = ty; r < 32; r += 8) {
        int n = nb + r, k = kb + tx;
        Bt[(size_t)n * NN + kperm2(k)] = __float2half_rn(tile[tx][r]);
    }
}

// ---------------------------------------------------------------------------
// Fused layer GEMM. outT (fp16, permuted, x2^6 folded into scale) or outR (f32).
// ---------------------------------------------------------------------------
__global__ void __launch_bounds__(256, 1)
gemm_layer(const float* __restrict__ A, const __half* __restrict__ Bt,
           __half* __restrict__ outT, float* __restrict__ outR, float scale) {
    extern __shared__ char smem[];
    __shared__ __align__(8) uint64_t mbar[2 * STAGES];

    const int tid  = threadIdx.x;
    const int lane = tid & 31;
    const int w    = tid >> 5;
    const int m0   = blockIdx.x * MT;
    const uint32_t sbase = smem_u32(smem);
    const uint32_t mb    = smem_u32(mbar);
    const int r4 = lane >> 2;
    const int c4 = lane & 3;

    if (tid == 0) {
        #pragma unroll
        for (int s = 0; s < STAGES; s++) {
            MBAR_INIT(mb + 8 * s, 128);                 // full
            MBAR_INIT(mb + 8 * (STAGES + s), 128);      // empty
        }
    }
    __syncthreads();

    if (w >= 4) {
        // ================= producers (warps 4-7) =================
        const int t = tid - 128;
        for (int it = 0; it < KIT; it++) {
            const int s = it & (STAGES - 1);
            const int r = it >> 3;
            if (r > 0) MBAR_WAIT(mb + 8 * (STAGES + s), (r - 1) & 1);
            const int k0 = it * KT;
            const uint32_t abase = sbase + (uint32_t)s * STG_B;
            const uint32_t bbase = abase + A_STG_B;
            #pragma unroll
            for (int j = 0; j < 4; j++) {               // A: 512 x 16B (fp32)
                int ch = t + 128 * j;
                int row = ch >> 3, cc = ch & 7;
                const float* src = A + (size_t)(m0 + row) * NN + k0 + cc * 4;
                CP_ASYNC16(abase + (uint32_t)(row * A_PITCH + cc * 16), src);
            }
            #pragma unroll
            for (int j = 0; j < 4; j++) {               // B: 512 x 16B (fp16)
                int ch = t + 128 * j;
                int col = ch >> 2, q = ch & 3;
                const __half* src = Bt + (size_t)col * NN + k0 + q * 8;
                CP_ASYNC16(bbase + (uint32_t)(col * B_PITCH + q * 16), src);
            }
            CP_ASYNC_MBAR_ARRIVE(mb + 8 * s);
        }
        return;
    }

    // ================= MMA warps (0-3): 32 rows x 64 cols =================
    const int wm = w >> 1;
    const int wn = w & 1;

    float acc[2][8][4];
    #pragma unroll
    for (int mi = 0; mi < 2; mi++)
        #pragma unroll
        for (int ni = 0; ni < 8; ni++)
            #pragma unroll
            for (int j = 0; j < 4; j++) acc[mi][ni][j] = 0.f;

    const uint32_t aoff = (uint32_t)((wm * 32 + r4) * A_PITCH + 8 * c4);
    const uint32_t boff = (uint32_t)((wn * 64 + r4) * B_PITCH + 16 * c4);

    // A half h of stage s -> 8 fp16x2 regs (scaled x2^13)
    auto loadA = [&](int s, int h, uint32_t (&aH)[4][2]) {
        const uint32_t base = sbase + (uint32_t)s * STG_B + aoff + h * 64;
        #pragma unroll
        for (int g = 0; g < 4; g++) {
            const float2* p =
                (const float2*)(size_t)0;   // placeholder (smem generic below)
            (void)p;
            float2 lo = *(const float2*)(smem + (base - sbase) + g * 8 * A_PITCH);
            float2 hi = *(const float2*)(smem + (base - sbase) + g * 8 * A_PITCH + 32);
            aH[g][0] = pack_h2(lo.x * 8192.0f, lo.y * 8192.0f);
            aH[g][1] = pack_h2(hi.x * 8192.0f, hi.y * 8192.0f);
        }
    };

    // full-stage B -> 8 x uint4 (x=h0b0, y=h0b1, z=h1b0, w=h1b1)
    auto loadB = [&](int s, uint4 (&bS)[8]) {
        const char* base = smem + (size_t)s * STG_B + A_STG_B + boff;
        #pragma unroll
        for (int g = 0; g < 8; g++)
            bS[g] = *(const uint4*)(base + g * 8 * B_PITCH);
    };

    auto mma_half = [&](uint32_t (&aH)[4][2], uint4 (&bS)[8], int h) {
        #pragma unroll
        for (int ni = 0; ni < 8; ni++) {
            uint32_t b0 = h ? bS[ni].z : bS[ni].x;
            uint32_t b1 = h ? bS[ni].w : bS[ni].y;
            {
                uint32_t af[4] = { aH[0][0], aH[1][0], aH[0][1], aH[1][1] };
                mma_f16(acc[0][ni], af, b0, b1);
            }
            {
                uint32_t af[4] = { aH[2][0], aH[3][0], aH[2][1], aH[3][1] };
                mma_f16(acc[1][ni], af, b0, b1);
            }
        }
    };

    uint32_t A0[4][2], A1[4][2];
    uint4    Bb[2][8];

    MBAR_WAIT(mb + 0, 0);
    loadB(0, Bb[0]);
    loadA(0, 0, A0);

    #pragma unroll 2
    for (int it = 0; it < KIT; it++) {
        const int s = it & (STAGES - 1);
        const int cur = it & 1, nxt = cur ^ 1;

        loadA(s, 1, A1);
        mma_half(A0, Bb[cur], 0);

        if (it + 1 < KIT) {
            const int s1 = (it + 1) & (STAGES - 1);
            MBAR_WAIT(mb + 8 * s1, ((it + 1) >> 3) & 1);
            loadB(s1, Bb[nxt]);
            loadA(s1, 0, A0);
        }
        mma_half(A1, Bb[cur], 1);

        MBAR_ARRIVE(mb + 8 * (STAGES + s));
    }

    // ---- epilogue ----
    const int rBase = m0 + wm * 32 + r4;
    const int cBase = wn * 64 + c4 * 2;
    #pragma unroll
    for (int mi = 0; mi < 2; mi++) {
        #pragma unroll
        for (int ni = 0; ni < 8; ni++) {
            #pragma unroll
            for (int j = 0; j < 4; j++) {
                int row = rBase + mi * 16 + (j >> 1) * 8;
                int col = cBase + ni * 8 + (j & 1);
                float v = acc[mi][ni][j] * scale;
                if (col < 64) v = fmaxf(v, 0.0f);
                if (outT) outT[(size_t)col * NN + kperm2(row)] = __float2half_rn(v);
                else      outR[(size_t)row * NB + col] = v;
            }
        }
    }
}

// ---------------------------------------------------------------------------
extern "C" void kernel_launch(void* const* d_in, const int* in_sizes, int n_in,
                              void* d_out, int out_size) {
    (void)in_sizes; (void)n_in; (void)out_size;
    const float* A = (const float*)d_in[0];
    const float* F = (const float*)d_in[1];
    const float* G = (const float*)d_in[2];
    float* out = (float*)d_out;

    __half *bt1 = nullptr, *bt2 = nullptr;
    cudaGetSymbolAddress((void**)&bt1, g_bth1);
    cudaGetSymbolAddress((void**)&bt2, g_bth2);

    cudaFuncSetAttribute(gemm_layer,
                         cudaFuncAttributeMaxDynamicSharedMemorySize, SMEM_BYTES);

    dim3 pb(32, 8), pg(NN / 32, NB / 32);
    pack_bt_kernel<<<pg, pb>>>(F, G, bt1);

    // layer 1: acc = (2^13 A) @ B ; store fp16( acc * 2^-7 ) = 2^6 * (A@B)
    gemm_layer<<<NN / MT, 256, SMEM_BYTES>>>(A, bt1, bt2, nullptr, 0.0078125f);
    // layer 2: acc = (2^13 A) @ (2^6 h) ; out = acc * 2^-19
    gemm_layer<<<NN / MT, 256, SMEM_BYTES>>>(A, bt2, nullptr, out,
                                             1.0f / 524288.0f);
}